// round 1
// baseline (speedup 1.0000x reference)
#include <cuda_runtime.h>

// ---------------------------------------------------------------------------
// AttnBlock: qkv = conv3x3(x); attention over HW=1024 tokens, C=512; proj 1x1;
// out = x + proj(attn). B=16, C=512, H=W=32.
// Round 0: fp32 SGEMM-style baseline (128x128x8 tiles, 8x8 per thread).
// ---------------------------------------------------------------------------

#define BM 128
#define BN 128
#define BK 8
#define PAD 4

#define Bsz 16
#define C 512
#define HW 1024
#define C3 1536
#define KTOT 4608   // 512*9

// Scratch (device globals; no allocation allowed)
__device__ float g_wpack[C3 * KTOT];              // 28 MB  [oc][tap][ic]
__device__ float g_qkv[Bsz * C3 * HW];            // 96 MB  [b][3C][HW]
__device__ float g_scores[Bsz * HW * HW];         // 64 MB  [b][qn][km]
__device__ float g_h[Bsz * HW * C];               // 32 MB  [b][qn][c]

// ---------------------------------------------------------------------------
// Pack w_qkv [oc][ic][kh][kw] -> [oc][tap][ic], tap = kh*3+kw
// ---------------------------------------------------------------------------
__global__ void pack_w_kernel(const float* __restrict__ w) {
    int i = blockIdx.x * blockDim.x + threadIdx.x;
    if (i >= C3 * KTOT) return;
    int oc = i / KTOT;
    int r = i - oc * KTOT;
    int tap = r >> 9;       // r / 512
    int ic = r & 511;
    g_wpack[i] = w[oc * KTOT + ic * 9 + tap];
}

// ---------------------------------------------------------------------------
// conv3x3 implicit GEMM: C[oc][p] = sum_k A[oc][k] * B[k][p] + bias
// A = g_wpack row-major [1536, 4608]; B gathered from x with zero padding.
// ---------------------------------------------------------------------------
__global__ __launch_bounds__(256, 2)
void conv_qkv_kernel(const float* __restrict__ x, const float* __restrict__ bias) {
    __shared__ __align__(16) float As[BK][BM + PAD];
    __shared__ __align__(16) float Bs[BK][BN + PAD];
    const int b = blockIdx.z;
    const int m0 = blockIdx.y * BM;
    const int n0 = blockIdx.x * BN;
    const int tid = threadIdx.x;
    const int tx = tid & 15, ty = tid >> 4;
    const float* xb = x + b * C * HW;

    float acc[8][8];
#pragma unroll
    for (int i = 0; i < 8; i++)
#pragma unroll
        for (int j = 0; j < 8; j++) acc[i][j] = 0.f;

    for (int k0 = 0; k0 < KTOT; k0 += BK) {
        // A tile: row-major [M,K]
#pragma unroll
        for (int j = 0; j < 4; j++) {
            int idx = tid + j * 256;
            int mm = idx >> 3, kk = idx & 7;
            As[kk][mm] = g_wpack[(m0 + mm) * KTOT + k0 + kk];
        }
        // B tile: gather. tap constant within a BK=8 chunk (512 % 8 == 0).
        const int tap = k0 >> 9;
        const int dh = tap / 3 - 1, dw = tap % 3 - 1;
        const int icbase = k0 & 511;
#pragma unroll
        for (int j = 0; j < 4; j++) {
            int idx = tid + j * 256;
            int kk = idx >> 7, nn = idx & 127;
            int ic = icbase + kk;
            int p = n0 + nn;
            int hh = (p >> 5) + dh;
            int ww = (p & 31) + dw;
            float v = 0.f;
            if ((unsigned)hh < 32u && (unsigned)ww < 32u)
                v = xb[(ic << 10) + (hh << 5) + ww];
            Bs[kk][nn] = v;
        }
        __syncthreads();
#pragma unroll
        for (int kk = 0; kk < BK; kk++) {
            float4 a0 = *(const float4*)&As[kk][ty * 8];
            float4 a1 = *(const float4*)&As[kk][ty * 8 + 4];
            float4 b0 = *(const float4*)&Bs[kk][tx * 8];
            float4 b1 = *(const float4*)&Bs[kk][tx * 8 + 4];
            float a[8] = {a0.x, a0.y, a0.z, a0.w, a1.x, a1.y, a1.z, a1.w};
            float bb[8] = {b0.x, b0.y, b0.z, b0.w, b1.x, b1.y, b1.z, b1.w};
#pragma unroll
            for (int i = 0; i < 8; i++)
#pragma unroll
                for (int j = 0; j < 8; j++) acc[i][j] += a[i] * bb[j];
        }
        __syncthreads();
    }
    float* outp = g_qkv + b * C3 * HW;
#pragma unroll
    for (int i = 0; i < 8; i++) {
        int m = m0 + ty * 8 + i;
        float bv = bias[m];
#pragma unroll
        for (int j = 0; j < 8; j++)
            outp[m * HW + n0 + tx * 8 + j] = acc[i][j] + bv;
    }
}

// ---------------------------------------------------------------------------
// scores[qn][km] = scale * sum_c q[c][qn] * k[c][km]   (TN GEMM, K=512)
// ---------------------------------------------------------------------------
__global__ __launch_bounds__(256, 2)
void scores_kernel() {
    __shared__ __align__(16) float As[BK][BM + PAD];
    __shared__ __align__(16) float Bs[BK][BN + PAD];
    const int b = blockIdx.z;
    const int m0 = blockIdx.y * BM;   // q pixel
    const int n0 = blockIdx.x * BN;   // k pixel
    const int tid = threadIdx.x;
    const int tx = tid & 15, ty = tid >> 4;
    const float* q = g_qkv + b * C3 * HW;        // [512][1024]
    const float* km = q + C * HW;                // k section

    float acc[8][8];
#pragma unroll
    for (int i = 0; i < 8; i++)
#pragma unroll
        for (int j = 0; j < 8; j++) acc[i][j] = 0.f;

    for (int k0 = 0; k0 < C; k0 += BK) {
#pragma unroll
        for (int j = 0; j < 4; j++) {
            int idx = tid + j * 256;
            int kk = idx >> 7, mm = idx & 127;
            As[kk][mm] = q[(k0 + kk) * HW + m0 + mm];
            Bs[kk][mm] = km[(k0 + kk) * HW + n0 + mm];
        }
        __syncthreads();
#pragma unroll
        for (int kk = 0; kk < BK; kk++) {
            float4 a0 = *(const float4*)&As[kk][ty * 8];
            float4 a1 = *(const float4*)&As[kk][ty * 8 + 4];
            float4 b0 = *(const float4*)&Bs[kk][tx * 8];
            float4 b1 = *(const float4*)&Bs[kk][tx * 8 + 4];
            float a[8] = {a0.x, a0.y, a0.z, a0.w, a1.x, a1.y, a1.z, a1.w};
            float bb[8] = {b0.x, b0.y, b0.z, b0.w, b1.x, b1.y, b1.z, b1.w};
#pragma unroll
            for (int i = 0; i < 8; i++)
#pragma unroll
                for (int j = 0; j < 8; j++) acc[i][j] += a[i] * bb[j];
        }
        __syncthreads();
    }
    const float scale = 0.044194173824159216f;   // 512^-0.5
    float* sp = g_scores + b * HW * HW;
#pragma unroll
    for (int i = 0; i < 8; i++) {
        int m = m0 + ty * 8 + i;
#pragma unroll
        for (int j = 0; j < 8; j++)
            sp[m * HW + n0 + tx * 8 + j] = acc[i][j] * scale;
    }
}

// ---------------------------------------------------------------------------
// Softmax over last axis (1024), one block of 256 threads per row.
// ---------------------------------------------------------------------------
__global__ void softmax_kernel() {
    float* s = g_scores + (size_t)blockIdx.x * HW;
    const int tid = threadIdx.x;
    const int lane = tid & 31, wid = tid >> 5;
    __shared__ float red[32];

    float4 v = ((float4*)s)[tid];
    float mx = fmaxf(fmaxf(v.x, v.y), fmaxf(v.z, v.w));
#pragma unroll
    for (int o = 16; o; o >>= 1) mx = fmaxf(mx, __shfl_xor_sync(0xffffffffu, mx, o));
    if (lane == 0) red[wid] = mx;
    __syncthreads();
    if (wid == 0) {
        float t = (lane < 8) ? red[lane] : -3.4e38f;
#pragma unroll
        for (int o = 4; o; o >>= 1) t = fmaxf(t, __shfl_xor_sync(0xffffffffu, t, o));
        if (lane == 0) red[0] = t;
    }
    __syncthreads();
    mx = red[0];
    __syncthreads();

    float4 e;
    e.x = expf(v.x - mx); e.y = expf(v.y - mx);
    e.z = expf(v.z - mx); e.w = expf(v.w - mx);
    float sum = e.x + e.y + e.z + e.w;
#pragma unroll
    for (int o = 16; o; o >>= 1) sum += __shfl_xor_sync(0xffffffffu, sum, o);
    if (lane == 0) red[wid] = sum;
    __syncthreads();
    if (wid == 0) {
        float t = (lane < 8) ? red[lane] : 0.f;
#pragma unroll
        for (int o = 4; o; o >>= 1) t += __shfl_xor_sync(0xffffffffu, t, o);
        if (lane == 0) red[0] = t;
    }
    __syncthreads();
    float inv = 1.0f / red[0];
    e.x *= inv; e.y *= inv; e.z *= inv; e.w *= inv;
    ((float4*)s)[tid] = e;
}

// ---------------------------------------------------------------------------
// h[qn][c] = sum_m attn[qn][m] * v[c][m]   (NT GEMM: A [M,K], B [N,K], K=1024)
// ---------------------------------------------------------------------------
__global__ __launch_bounds__(256, 2)
void av_kernel() {
    __shared__ __align__(16) float As[BK][BM + PAD];
    __shared__ __align__(16) float Bs[BK][BN + PAD];
    const int b = blockIdx.z;
    const int m0 = blockIdx.y * BM;   // qn
    const int n0 = blockIdx.x * BN;   // c
    const int tid = threadIdx.x;
    const int tx = tid & 15, ty = tid >> 4;
    const float* attn = g_scores + b * HW * HW;
    const float* v = g_qkv + b * C3 * HW + 2 * C * HW;   // [512][1024]

    float acc[8][8];
#pragma unroll
    for (int i = 0; i < 8; i++)
#pragma unroll
        for (int j = 0; j < 8; j++) acc[i][j] = 0.f;

    for (int k0 = 0; k0 < HW; k0 += BK) {
#pragma unroll
        for (int j = 0; j < 4; j++) {
            int idx = tid + j * 256;
            int mm = idx >> 3, kk = idx & 7;
            As[kk][mm] = attn[(m0 + mm) * HW + k0 + kk];
            Bs[kk][mm] = v[(n0 + mm) * HW + k0 + kk];
        }
        __syncthreads();
#pragma unroll
        for (int kk = 0; kk < BK; kk++) {
            float4 a0 = *(const float4*)&As[kk][ty * 8];
            float4 a1 = *(const float4*)&As[kk][ty * 8 + 4];
            float4 b0 = *(const float4*)&Bs[kk][tx * 8];
            float4 b1 = *(const float4*)&Bs[kk][tx * 8 + 4];
            float a[8] = {a0.x, a0.y, a0.z, a0.w, a1.x, a1.y, a1.z, a1.w};
            float bb[8] = {b0.x, b0.y, b0.z, b0.w, b1.x, b1.y, b1.z, b1.w};
#pragma unroll
            for (int i = 0; i < 8; i++)
#pragma unroll
                for (int j = 0; j < 8; j++) acc[i][j] += a[i] * bb[j];
        }
        __syncthreads();
    }
    float* hp = g_h + b * HW * C;
#pragma unroll
    for (int i = 0; i < 8; i++) {
        int m = m0 + ty * 8 + i;
#pragma unroll
        for (int j = 0; j < 8; j++)
            hp[m * C + n0 + tx * 8 + j] = acc[i][j];
    }
}

// ---------------------------------------------------------------------------
// out[co][p] = x[co][p] + b_proj[co] + sum_ci w_proj[co][ci] * h[p][ci]
// (NT GEMM: A [M=512,K=512], B [N=1024,K=512])
// ---------------------------------------------------------------------------
__global__ __launch_bounds__(256, 2)
void proj_kernel(const float* __restrict__ x, const float* __restrict__ wproj,
                 const float* __restrict__ bproj, float* __restrict__ out) {
    __shared__ __align__(16) float As[BK][BM + PAD];
    __shared__ __align__(16) float Bs[BK][BN + PAD];
    const int b = blockIdx.z;
    const int m0 = blockIdx.y * BM;   // co
    const int n0 = blockIdx.x * BN;   // p
    const int tid = threadIdx.x;
    const int tx = tid & 15, ty = tid >> 4;
    const float* hp = g_h + b * HW * C;

    float acc[8][8];
#pragma unroll
    for (int i = 0; i < 8; i++)
#pragma unroll
        for (int j = 0; j < 8; j++) acc[i][j] = 0.f;

    for (int k0 = 0; k0 < C; k0 += BK) {
#pragma unroll
        for (int j = 0; j < 4; j++) {
            int idx = tid + j * 256;
            int mm = idx >> 3, kk = idx & 7;
            As[kk][mm] = wproj[(m0 + mm) * C + k0 + kk];
            Bs[kk][mm] = hp[(n0 + mm) * C + k0 + kk];
        }
        __syncthreads();
#pragma unroll
        for (int kk = 0; kk < BK; kk++) {
            float4 a0 = *(const float4*)&As[kk][ty * 8];
            float4 a1 = *(const float4*)&As[kk][ty * 8 + 4];
            float4 b0 = *(const float4*)&Bs[kk][tx * 8];
            float4 b1 = *(const float4*)&Bs[kk][tx * 8 + 4];
            float a[8] = {a0.x, a0.y, a0.z, a0.w, a1.x, a1.y, a1.z, a1.w};
            float bb[8] = {b0.x, b0.y, b0.z, b0.w, b1.x, b1.y, b1.z, b1.w};
#pragma unroll
            for (int i = 0; i < 8; i++)
#pragma unroll
                for (int j = 0; j < 8; j++) acc[i][j] += a[i] * bb[j];
        }
        __syncthreads();
    }
    const float* xb = x + b * C * HW;
    float* ob = out + b * C * HW;
#pragma unroll
    for (int i = 0; i < 8; i++) {
        int m = m0 + ty * 8 + i;
        float bv = bproj[m];
#pragma unroll
        for (int j = 0; j < 8; j++) {
            int n = n0 + tx * 8 + j;
            ob[m * HW + n] = xb[m * HW + n] + bv + acc[i][j];
        }
    }
}

// ---------------------------------------------------------------------------
extern "C" void kernel_launch(void* const* d_in, const int* in_sizes, int n_in,
                              void* d_out, int out_size) {
    const float* x      = (const float*)d_in[0];
    const float* w_qkv  = (const float*)d_in[1];
    const float* b_qkv  = (const float*)d_in[2];
    const float* w_proj = (const float*)d_in[3];
    const float* b_proj = (const float*)d_in[4];
    // d_in[5] gn_gamma, d_in[6] gn_beta: dead in the reference graph
    float* out = (float*)d_out;

    pack_w_kernel<<<(C3 * KTOT + 255) / 256, 256>>>(w_qkv);
    conv_qkv_kernel<<<dim3(HW / BN, C3 / BM, Bsz), 256>>>(x, b_qkv);
    scores_kernel<<<dim3(HW / BN, HW / BM, Bsz), 256>>>();
    softmax_kernel<<<Bsz * HW, 256>>>();
    av_kernel<<<dim3(C / BN, HW / BM, Bsz), 256>>>();
    proj_kernel<<<dim3(HW / BN, C / BM, Bsz), 256>>>(x, w_proj, b_proj, out);
}

// round 2
// speedup vs baseline: 6.2083x; 6.2083x over previous
#include <cuda_runtime.h>
#include <cuda_bf16.h>

// ---------------------------------------------------------------------------
// AttnBlock, Round 1: bf16 tensor-core (mma.sync m16n8k16) for all GEMMs.
// B=16, C=512, H=W=32 (HW=1024). out = x + proj1x1(attn(conv3x3_qkv(x))).
// ---------------------------------------------------------------------------

#define Bsz 16
#define C 512
#define HW 1024
#define C3 1536
#define KTOT 4608        // 512*9

#define BM 128
#define BN 128
#define BK 32
#define BKP 40           // [rows][BK+8]  (pad keeps 16B align, conflict-free ldmatrix)
#define SP  136          // [BK][128+8]

// Scratch: device globals (no allocation allowed)
__device__ __nv_bfloat16 g_wpack[C3 * KTOT];                 // [oc][tap][ic] bf16
__device__ __nv_bfloat16 g_wproj[C * C];                     // bf16
__device__ __nv_bfloat16 g_im2col[(size_t)Bsz * KTOT * HW];  // [b][k=tap*512+ic][p]
__device__ __nv_bfloat16 g_qkv[(size_t)Bsz * C3 * HW];       // [b][3C][p]
__device__ float         g_scores[(size_t)Bsz * HW * HW];    // [b][qn][km] fp32
__device__ __nv_bfloat16 g_attn[(size_t)Bsz * HW * HW];      // softmaxed, bf16
__device__ __nv_bfloat16 g_h[(size_t)Bsz * HW * C];          // [b][qn][c]

// ---------------------------------------------------------------------------
// PTX helpers
// ---------------------------------------------------------------------------
__device__ __forceinline__ unsigned su32(const void* p) {
    unsigned a;
    asm("{ .reg .u64 t; cvta.to.shared.u64 t, %1; cvt.u32.u64 %0, t; }"
        : "=r"(a) : "l"(p));
    return a;
}
__device__ __forceinline__ void ldsm_x4(unsigned* r, unsigned addr) {
    asm volatile("ldmatrix.sync.aligned.m8n8.x4.shared.b16 {%0,%1,%2,%3}, [%4];"
                 : "=r"(r[0]), "=r"(r[1]), "=r"(r[2]), "=r"(r[3]) : "r"(addr));
}
__device__ __forceinline__ void ldsm_x4_t(unsigned* r, unsigned addr) {
    asm volatile("ldmatrix.sync.aligned.m8n8.x4.trans.shared.b16 {%0,%1,%2,%3}, [%4];"
                 : "=r"(r[0]), "=r"(r[1]), "=r"(r[2]), "=r"(r[3]) : "r"(addr));
}
__device__ __forceinline__ void mma16816(float* d, const unsigned* a, const unsigned* b) {
    asm volatile(
        "mma.sync.aligned.m16n8k16.row.col.f32.bf16.bf16.f32 "
        "{%0,%1,%2,%3},{%4,%5,%6,%7},{%8,%9},{%0,%1,%2,%3};"
        : "+f"(d[0]), "+f"(d[1]), "+f"(d[2]), "+f"(d[3])
        : "r"(a[0]), "r"(a[1]), "r"(a[2]), "r"(a[3]), "r"(b[0]), "r"(b[1]));
}

// Process one BK=32 slab. AT: A smem is [BK][128+8] (k-major, trans ldmatrix);
// else [BM][BK+8]. BT likewise for B.
template <bool AT, bool BT>
__device__ __forceinline__ void mma_block(unsigned aB, unsigned bB,
                                          float acc[2][8][4], int lane, int wm, int wn) {
    const int g = lane >> 3, r = lane & 7;
#pragma unroll
    for (int ks = 0; ks < 2; ks++) {
        const int k = ks * 16;
        unsigned a[2][4];
#pragma unroll
        for (int mi = 0; mi < 2; mi++) {
            const int mt = wm * 32 + mi * 16;
            if (AT) {
                unsigned off = ((k + (g >> 1) * 8 + r) * SP + mt + (g & 1) * 8) * 2;
                ldsm_x4_t(a[mi], aB + off);
            } else {
                unsigned off = ((mt + (g & 1) * 8 + r) * BKP + k + (g >> 1) * 8) * 2;
                ldsm_x4(a[mi], aB + off);
            }
        }
        unsigned bf[8][2];
#pragma unroll
        for (int nj = 0; nj < 4; nj++) {
            const int nt = wn * 64 + nj * 16;
            unsigned t[4];
            if (BT) {
                unsigned off = ((k + (g & 1) * 8 + r) * SP + nt + (g >> 1) * 8) * 2;
                ldsm_x4_t(t, bB + off);
            } else {
                unsigned off = ((nt + (g >> 1) * 8 + r) * BKP + k + (g & 1) * 8) * 2;
                ldsm_x4(t, bB + off);
            }
            bf[nj * 2][0] = t[0]; bf[nj * 2][1] = t[1];
            bf[nj * 2 + 1][0] = t[2]; bf[nj * 2 + 1][1] = t[3];
        }
#pragma unroll
        for (int mi = 0; mi < 2; mi++)
#pragma unroll
            for (int n = 0; n < 8; n++) mma16816(acc[mi][n], a[mi], bf[n]);
    }
}

// ---------------------------------------------------------------------------
// Prep kernels
// ---------------------------------------------------------------------------
__global__ void pack_w_kernel(const float* __restrict__ w) {
    int i = blockIdx.x * blockDim.x + threadIdx.x;
    if (i >= C3 * KTOT) return;
    int oc = i / KTOT;
    int r = i - oc * KTOT;
    int tap = r >> 9, ic = r & 511;
    g_wpack[i] = __float2bfloat16(w[oc * KTOT + ic * 9 + tap]);
}
__global__ void pack_wproj_kernel(const float* __restrict__ w) {
    int i = blockIdx.x * blockDim.x + threadIdx.x;
    if (i < C * C) g_wproj[i] = __float2bfloat16(w[i]);
}
// im2col: [b][k=tap*512+ic][p] bf16; each thread does 8 consecutive p (same h-row).
__global__ void im2col_kernel(const float* __restrict__ x) {
    size_t idx = (size_t)blockIdx.x * blockDim.x + threadIdx.x;
    if (idx >= (size_t)Bsz * KTOT * 128) return;
    int chunk = (int)(idx & 127);
    size_t t = idx >> 7;
    int k = (int)(t % KTOT);
    int b = (int)(t / KTOT);
    int tap = k >> 9, ic = k & 511;
    int dh = tap / 3 - 1, dw = tap % 3 - 1;
    int p0 = chunk * 8;
    int h = (p0 >> 5) + dh;
    int w0 = (p0 & 31) + dw;
    const float* xr = x + ((size_t)b * C + ic) * HW;
    __nv_bfloat16 v[8];
    bool hok = ((unsigned)h < 32u);
#pragma unroll
    for (int j = 0; j < 8; j++) {
        int w = w0 + j;
        float f = (hok && (unsigned)w < 32u) ? __ldg(&xr[(h << 5) + w]) : 0.f;
        v[j] = __float2bfloat16(f);
    }
    *(uint4*)&g_im2col[((size_t)b * KTOT + k) * HW + p0] = *(uint4*)v;
}

// ---------------------------------------------------------------------------
// conv3x3 as GEMM: qkv[m=oc][n=p] = wpack[m][k] @ im2col[k][n] + bias  (bf16 out)
// ---------------------------------------------------------------------------
__global__ __launch_bounds__(256, 2)
void conv_mma(const float* __restrict__ bias) {
    __shared__ __align__(16) __nv_bfloat16 As[BM * BKP];
    __shared__ __align__(16) __nv_bfloat16 Bs[BK * SP];
    const int b = blockIdx.z, m0 = blockIdx.y * BM, n0 = blockIdx.x * BN;
    const int tid = threadIdx.x, lane = tid & 31, wid = tid >> 5;
    const int wm = wid >> 1, wn = wid & 1;
    const __nv_bfloat16* A = g_wpack;
    const __nv_bfloat16* Bm = g_im2col + (size_t)b * KTOT * HW;

    float acc[2][8][4];
#pragma unroll
    for (int i = 0; i < 2; i++)
#pragma unroll
        for (int j = 0; j < 8; j++)
#pragma unroll
            for (int q = 0; q < 4; q++) acc[i][j][q] = 0.f;

    unsigned aB = su32(As), bB = su32(Bs);
    for (int k0 = 0; k0 < KTOT; k0 += BK) {
#pragma unroll
        for (int i = 0; i < 2; i++) {
            int u = tid + i * 256, row = u >> 2, q = u & 3;
            *(uint4*)&As[row * BKP + q * 8] =
                *(const uint4*)&A[(size_t)(m0 + row) * KTOT + k0 + q * 8];
        }
#pragma unroll
        for (int i = 0; i < 2; i++) {
            int u = tid + i * 256, row = u >> 4, q = u & 15;
            *(uint4*)&Bs[row * SP + q * 8] =
                *(const uint4*)&Bm[(size_t)(k0 + row) * HW + n0 + q * 8];
        }
        __syncthreads();
        mma_block<false, true>(aB, bB, acc, lane, wm, wn);
        __syncthreads();
    }
    __nv_bfloat16* out = g_qkv + (size_t)b * C3 * HW;
    const int rr = lane >> 2, cc = (lane & 3) * 2;
#pragma unroll
    for (int mi = 0; mi < 2; mi++) {
        int gr = m0 + wm * 32 + mi * 16 + rr;
        float b0v = bias[gr], b1v = bias[gr + 8];
#pragma unroll
        for (int n = 0; n < 8; n++) {
            int gc = n0 + wn * 64 + n * 8 + cc;
            *(__nv_bfloat162*)&out[(size_t)gr * HW + gc] =
                __floats2bfloat162_rn(acc[mi][n][0] + b0v, acc[mi][n][1] + b0v);
            *(__nv_bfloat162*)&out[(size_t)(gr + 8) * HW + gc] =
                __floats2bfloat162_rn(acc[mi][n][2] + b1v, acc[mi][n][3] + b1v);
        }
    }
}

// ---------------------------------------------------------------------------
// scores[qn][km] = scale * q^T k ;  q,k are [c][p] (k-major for both operands)
// ---------------------------------------------------------------------------
__global__ __launch_bounds__(256, 2)
void scores_mma() {
    __shared__ __align__(16) __nv_bfloat16 As[BK * SP];
    __shared__ __align__(16) __nv_bfloat16 Bs[BK * SP];
    const int b = blockIdx.z, m0 = blockIdx.y * BM, n0 = blockIdx.x * BN;
    const int tid = threadIdx.x, lane = tid & 31, wid = tid >> 5;
    const int wm = wid >> 1, wn = wid & 1;
    const __nv_bfloat16* q = g_qkv + (size_t)b * C3 * HW;
    const __nv_bfloat16* km = q + (size_t)C * HW;

    float acc[2][8][4];
#pragma unroll
    for (int i = 0; i < 2; i++)
#pragma unroll
        for (int j = 0; j < 8; j++)
#pragma unroll
            for (int qq = 0; qq < 4; qq++) acc[i][j][qq] = 0.f;

    unsigned aB = su32(As), bB = su32(Bs);
    for (int k0 = 0; k0 < C; k0 += BK) {
#pragma unroll
        for (int i = 0; i < 2; i++) {
            int u = tid + i * 256, row = u >> 4, qd = u & 15;
            *(uint4*)&As[row * SP + qd * 8] =
                *(const uint4*)&q[(size_t)(k0 + row) * HW + m0 + qd * 8];
            *(uint4*)&Bs[row * SP + qd * 8] =
                *(const uint4*)&km[(size_t)(k0 + row) * HW + n0 + qd * 8];
        }
        __syncthreads();
        mma_block<true, true>(aB, bB, acc, lane, wm, wn);
        __syncthreads();
    }
    const float scale = 0.044194173824159216f;   // 512^-0.5
    float* sp = g_scores + (size_t)b * HW * HW;
    const int rr = lane >> 2, cc = (lane & 3) * 2;
#pragma unroll
    for (int mi = 0; mi < 2; mi++) {
        int gr = m0 + wm * 32 + mi * 16 + rr;
#pragma unroll
        for (int n = 0; n < 8; n++) {
            int gc = n0 + wn * 64 + n * 8 + cc;
            *(float2*)&sp[(size_t)gr * HW + gc] =
                make_float2(acc[mi][n][0] * scale, acc[mi][n][1] * scale);
            *(float2*)&sp[(size_t)(gr + 8) * HW + gc] =
                make_float2(acc[mi][n][2] * scale, acc[mi][n][3] * scale);
        }
    }
}

// ---------------------------------------------------------------------------
// Softmax over last axis (1024); fp32 in, bf16 out.
// ---------------------------------------------------------------------------
__global__ void softmax_kernel() {
    const float* s = g_scores + (size_t)blockIdx.x * HW;
    __nv_bfloat16* a = g_attn + (size_t)blockIdx.x * HW;
    const int tid = threadIdx.x, lane = tid & 31, wid = tid >> 5;
    __shared__ float red[32];

    float4 v = ((const float4*)s)[tid];
    float mx = fmaxf(fmaxf(v.x, v.y), fmaxf(v.z, v.w));
#pragma unroll
    for (int o = 16; o; o >>= 1) mx = fmaxf(mx, __shfl_xor_sync(0xffffffffu, mx, o));
    if (lane == 0) red[wid] = mx;
    __syncthreads();
    if (wid == 0) {
        float t = (lane < 8) ? red[lane] : -3.4e38f;
#pragma unroll
        for (int o = 4; o; o >>= 1) t = fmaxf(t, __shfl_xor_sync(0xffffffffu, t, o));
        if (lane == 0) red[0] = t;
    }
    __syncthreads();
    mx = red[0];
    __syncthreads();

    float4 e;
    e.x = expf(v.x - mx); e.y = expf(v.y - mx);
    e.z = expf(v.z - mx); e.w = expf(v.w - mx);
    float sum = e.x + e.y + e.z + e.w;
#pragma unroll
    for (int o = 16; o; o >>= 1) sum += __shfl_xor_sync(0xffffffffu, sum, o);
    if (lane == 0) red[wid] = sum;
    __syncthreads();
    if (wid == 0) {
        float t = (lane < 8) ? red[lane] : 0.f;
#pragma unroll
        for (int o = 4; o; o >>= 1) t += __shfl_xor_sync(0xffffffffu, t, o);
        if (lane == 0) red[0] = t;
    }
    __syncthreads();
    float inv = 1.0f / red[0];
    __nv_bfloat162 p0 = __floats2bfloat162_rn(e.x * inv, e.y * inv);
    __nv_bfloat162 p1 = __floats2bfloat162_rn(e.z * inv, e.w * inv);
    ((__nv_bfloat162*)a)[tid * 2] = p0;
    ((__nv_bfloat162*)a)[tid * 2 + 1] = p1;
}

// ---------------------------------------------------------------------------
// h[qn][c] = attn[qn][m] @ v[c][m]^T   A:[m][k] nt,  B:[n][k] nt
// ---------------------------------------------------------------------------
__global__ __launch_bounds__(256, 2)
void av_mma() {
    __shared__ __align__(16) __nv_bfloat16 As[BM * BKP];
    __shared__ __align__(16) __nv_bfloat16 Bs[BN * BKP];
    const int b = blockIdx.z, m0 = blockIdx.y * BM, n0 = blockIdx.x * BN;
    const int tid = threadIdx.x, lane = tid & 31, wid = tid >> 5;
    const int wm = wid >> 1, wn = wid & 1;
    const __nv_bfloat16* attn = g_attn + (size_t)b * HW * HW;
    const __nv_bfloat16* v = g_qkv + (size_t)b * C3 * HW + (size_t)2 * C * HW;

    float acc[2][8][4];
#pragma unroll
    for (int i = 0; i < 2; i++)
#pragma unroll
        for (int j = 0; j < 8; j++)
#pragma unroll
            for (int q = 0; q < 4; q++) acc[i][j][q] = 0.f;

    unsigned aB = su32(As), bB = su32(Bs);
    for (int k0 = 0; k0 < HW; k0 += BK) {
#pragma unroll
        for (int i = 0; i < 2; i++) {
            int u = tid + i * 256, row = u >> 2, q = u & 3;
            *(uint4*)&As[row * BKP + q * 8] =
                *(const uint4*)&attn[(size_t)(m0 + row) * HW + k0 + q * 8];
            *(uint4*)&Bs[row * BKP + q * 8] =
                *(const uint4*)&v[(size_t)(n0 + row) * HW + k0 + q * 8];
        }
        __syncthreads();
        mma_block<false, false>(aB, bB, acc, lane, wm, wn);
        __syncthreads();
    }
    __nv_bfloat16* hp = g_h + (size_t)b * HW * C;
    const int rr = lane >> 2, cc = (lane & 3) * 2;
#pragma unroll
    for (int mi = 0; mi < 2; mi++) {
        int gr = m0 + wm * 32 + mi * 16 + rr;
#pragma unroll
        for (int n = 0; n < 8; n++) {
            int gc = n0 + wn * 64 + n * 8 + cc;
            *(__nv_bfloat162*)&hp[(size_t)gr * C + gc] =
                __floats2bfloat162_rn(acc[mi][n][0], acc[mi][n][1]);
            *(__nv_bfloat162*)&hp[(size_t)(gr + 8) * C + gc] =
                __floats2bfloat162_rn(acc[mi][n][2], acc[mi][n][3]);
        }
    }
}

// ---------------------------------------------------------------------------
// out[co][p] = x[co][p] + b_proj[co] + wproj[co][ci] @ h[p][ci]^T  (fp32 out)
// ---------------------------------------------------------------------------
__global__ __launch_bounds__(256, 2)
void proj_mma(const float* __restrict__ x, const float* __restrict__ bproj,
              float* __restrict__ out) {
    __shared__ __align__(16) __nv_bfloat16 As[BM * BKP];
    __shared__ __align__(16) __nv_bfloat16 Bs[BN * BKP];
    const int b = blockIdx.z, m0 = blockIdx.y * BM, n0 = blockIdx.x * BN;
    const int tid = threadIdx.x, lane = tid & 31, wid = tid >> 5;
    const int wm = wid >> 1, wn = wid & 1;
    const __nv_bfloat16* hp = g_h + (size_t)b * HW * C;

    float acc[2][8][4];
#pragma unroll
    for (int i = 0; i < 2; i++)
#pragma unroll
        for (int j = 0; j < 8; j++)
#pragma unroll
            for (int q = 0; q < 4; q++) acc[i][j][q] = 0.f;

    unsigned aB = su32(As), bB = su32(Bs);
    for (int k0 = 0; k0 < C; k0 += BK) {
#pragma unroll
        for (int i = 0; i < 2; i++) {
            int u = tid + i * 256, row = u >> 2, q = u & 3;
            *(uint4*)&As[row * BKP + q * 8] =
                *(const uint4*)&g_wproj[(size_t)(m0 + row) * C + k0 + q * 8];
            *(uint4*)&Bs[row * BKP + q * 8] =
                *(const uint4*)&hp[(size_t)(n0 + row) * C + k0 + q * 8];
        }
        __syncthreads();
        mma_block<false, false>(aB, bB, acc, lane, wm, wn);
        __syncthreads();
    }
    const float* xb = x + (size_t)b * C * HW;
    float* ob = out + (size_t)b * C * HW;
    const int rr = lane >> 2, cc = (lane & 3) * 2;
#pragma unroll
    for (int mi = 0; mi < 2; mi++) {
        int gr = m0 + wm * 32 + mi * 16 + rr;
        float b0v = bproj[gr], b1v = bproj[gr + 8];
#pragma unroll
        for (int n = 0; n < 8; n++) {
            int gc = n0 + wn * 64 + n * 8 + cc;
            float2 x0 = *(const float2*)&xb[(size_t)gr * HW + gc];
            float2 x1 = *(const float2*)&xb[(size_t)(gr + 8) * HW + gc];
            *(float2*)&ob[(size_t)gr * HW + gc] =
                make_float2(x0.x + b0v + acc[mi][n][0], x0.y + b0v + acc[mi][n][1]);
            *(float2*)&ob[(size_t)(gr + 8) * HW + gc] =
                make_float2(x1.x + b1v + acc[mi][n][2], x1.y + b1v + acc[mi][n][3]);
        }
    }
}

// ---------------------------------------------------------------------------
extern "C" void kernel_launch(void* const* d_in, const int* in_sizes, int n_in,
                              void* d_out, int out_size) {
    const float* x      = (const float*)d_in[0];
    const float* w_qkv  = (const float*)d_in[1];
    const float* b_qkv  = (const float*)d_in[2];
    const float* w_proj = (const float*)d_in[3];
    const float* b_proj = (const float*)d_in[4];
    float* out = (float*)d_out;

    pack_w_kernel<<<(C3 * KTOT + 255) / 256, 256>>>(w_qkv);
    pack_wproj_kernel<<<(C * C + 255) / 256, 256>>>(w_proj);
    {
        size_t total = (size_t)Bsz * KTOT * 128;   // 8 pixels per thread
        im2col_kernel<<<(unsigned)((total + 255) / 256), 256>>>(x);
    }
    conv_mma<<<dim3(HW / BN, C3 / BM, Bsz), 256>>>(b_qkv);
    scores_mma<<<dim3(HW / BN, HW / BM, Bsz), 256>>>();
    softmax_kernel<<<Bsz * HW, 256>>>();
    av_mma<<<dim3(C / BN, HW / BM, Bsz), 256>>>();
    proj_mma<<<dim3(HW / BN, C / BM, Bsz), 256>>>(x, b_proj, out);
}

// round 3
// speedup vs baseline: 7.7075x; 1.2415x over previous
#include <cuda_runtime.h>
#include <cuda_bf16.h>

// ---------------------------------------------------------------------------
// AttnBlock, Round 2: bf16 mma.sync GEMMs + cp.async double-buffered pipelines.
// B=16, C=512, H=W=32 (HW=1024). out = x + proj1x1(attn(conv3x3_qkv(x))).
// ---------------------------------------------------------------------------

#define Bsz 16
#define C 512
#define HW 1024
#define C3 1536
#define KTOT 4608        // 512*9

#define BM 128
#define BN 128
#define BK 32
#define BKP 40           // [rows][BK+8]
#define SP  136          // [BK][128+8]

// Scratch: device globals (no allocation allowed)
__device__ __nv_bfloat16 g_wpack[C3 * KTOT];                 // [oc][tap][ic] bf16
__device__ __nv_bfloat16 g_wproj[C * C];                     // bf16
__device__ __nv_bfloat16 g_im2col[(size_t)Bsz * KTOT * HW];  // [b][k=tap*512+ic][p]
__device__ __nv_bfloat16 g_qkv[(size_t)Bsz * C3 * HW];       // [b][3C][p]
__device__ float         g_scores[(size_t)Bsz * HW * HW];    // [b][qn][km] fp32
__device__ __nv_bfloat16 g_attn[(size_t)Bsz * HW * HW];      // softmaxed, bf16
__device__ __nv_bfloat16 g_h[(size_t)Bsz * HW * C];          // [b][qn][c]

// ---------------------------------------------------------------------------
// PTX helpers
// ---------------------------------------------------------------------------
__device__ __forceinline__ unsigned su32(const void* p) {
    unsigned a;
    asm("{ .reg .u64 t; cvta.to.shared.u64 t, %1; cvt.u32.u64 %0, t; }"
        : "=r"(a) : "l"(p));
    return a;
}
__device__ __forceinline__ void cp16(unsigned dst, const void* src) {
    asm volatile("cp.async.cg.shared.global [%0], [%1], 16;" :: "r"(dst), "l"(src));
}
#define CP_COMMIT() asm volatile("cp.async.commit_group;")
#define CP_WAIT0()  asm volatile("cp.async.wait_group 0;")

__device__ __forceinline__ void ldsm_x4(unsigned* r, unsigned addr) {
    asm volatile("ldmatrix.sync.aligned.m8n8.x4.shared.b16 {%0,%1,%2,%3}, [%4];"
                 : "=r"(r[0]), "=r"(r[1]), "=r"(r[2]), "=r"(r[3]) : "r"(addr));
}
__device__ __forceinline__ void ldsm_x4_t(unsigned* r, unsigned addr) {
    asm volatile("ldmatrix.sync.aligned.m8n8.x4.trans.shared.b16 {%0,%1,%2,%3}, [%4];"
                 : "=r"(r[0]), "=r"(r[1]), "=r"(r[2]), "=r"(r[3]) : "r"(addr));
}
__device__ __forceinline__ void mma16816(float* d, const unsigned* a, const unsigned* b) {
    asm volatile(
        "mma.sync.aligned.m16n8k16.row.col.f32.bf16.bf16.f32 "
        "{%0,%1,%2,%3},{%4,%5,%6,%7},{%8,%9},{%0,%1,%2,%3};"
        : "+f"(d[0]), "+f"(d[1]), "+f"(d[2]), "+f"(d[3])
        : "r"(a[0]), "r"(a[1]), "r"(a[2]), "r"(a[3]), "r"(b[0]), "r"(b[1]));
}

// Process one BK=32 slab. AT: A smem is [BK][128+8] (k-major, trans ldmatrix);
// else [BM][BK+8]. BT likewise for B.
template <bool AT, bool BT>
__device__ __forceinline__ void mma_block(unsigned aB, unsigned bB,
                                          float acc[2][8][4], int lane, int wm, int wn) {
    const int g = lane >> 3, r = lane & 7;
#pragma unroll
    for (int ks = 0; ks < 2; ks++) {
        const int k = ks * 16;
        unsigned a[2][4];
#pragma unroll
        for (int mi = 0; mi < 2; mi++) {
            const int mt = wm * 32 + mi * 16;
            if (AT) {
                unsigned off = ((k + (g >> 1) * 8 + r) * SP + mt + (g & 1) * 8) * 2;
                ldsm_x4_t(a[mi], aB + off);
            } else {
                unsigned off = ((mt + (g & 1) * 8 + r) * BKP + k + (g >> 1) * 8) * 2;
                ldsm_x4(a[mi], aB + off);
            }
        }
        unsigned bf[8][2];
#pragma unroll
        for (int nj = 0; nj < 4; nj++) {
            const int nt = wn * 64 + nj * 16;
            unsigned t[4];
            if (BT) {
                unsigned off = ((k + (g & 1) * 8 + r) * SP + nt + (g >> 1) * 8) * 2;
                ldsm_x4_t(t, bB + off);
            } else {
                unsigned off = ((nt + (g >> 1) * 8 + r) * BKP + k + (g & 1) * 8) * 2;
                ldsm_x4(t, bB + off);
            }
            bf[nj * 2][0] = t[0]; bf[nj * 2][1] = t[1];
            bf[nj * 2 + 1][0] = t[2]; bf[nj * 2 + 1][1] = t[3];
        }
#pragma unroll
        for (int mi = 0; mi < 2; mi++)
#pragma unroll
            for (int n = 0; n < 8; n++) mma16816(acc[mi][n], a[mi], bf[n]);
    }
}

// ---------------------------------------------------------------------------
// Prep kernels
// ---------------------------------------------------------------------------
__global__ void pack_w_kernel(const float* __restrict__ w) {
    int i = blockIdx.x * blockDim.x + threadIdx.x;
    if (i >= C3 * KTOT) return;
    int oc = i / KTOT;
    int r = i - oc * KTOT;
    int tap = r >> 9, ic = r & 511;
    g_wpack[i] = __float2bfloat16(w[oc * KTOT + ic * 9 + tap]);
}
__global__ void pack_wproj_kernel(const float* __restrict__ w) {
    int i = blockIdx.x * blockDim.x + threadIdx.x;
    if (i < C * C) g_wproj[i] = __float2bfloat16(w[i]);
}
// im2col: [b][k=tap*512+ic][p] bf16; each thread does 8 consecutive p (same h-row).
__global__ void im2col_kernel(const float* __restrict__ x) {
    size_t idx = (size_t)blockIdx.x * blockDim.x + threadIdx.x;
    if (idx >= (size_t)Bsz * KTOT * 128) return;
    int chunk = (int)(idx & 127);
    size_t t = idx >> 7;
    int k = (int)(t % KTOT);
    int b = (int)(t / KTOT);
    int tap = k >> 9, ic = k & 511;
    int dh = tap / 3 - 1, dw = tap % 3 - 1;
    int p0 = chunk * 8;
    int h = (p0 >> 5) + dh;
    int w0 = (p0 & 31) + dw;
    const float* xr = x + ((size_t)b * C + ic) * HW;
    __nv_bfloat16 v[8];
    bool hok = ((unsigned)h < 32u);
#pragma unroll
    for (int j = 0; j < 8; j++) {
        int w = w0 + j;
        float f = (hok && (unsigned)w < 32u) ? __ldg(&xr[(h << 5) + w]) : 0.f;
        v[j] = __float2bfloat16(f);
    }
    *(uint4*)&g_im2col[((size_t)b * KTOT + k) * HW + p0] = *(uint4*)v;
}

// ---------------------------------------------------------------------------
// conv3x3 as GEMM: qkv[m=oc][n=p] = wpack[m][k] @ im2col[k][n] + bias  (bf16 out)
// A: [M][K] row-major (nt), B: [K][N] k-major (trans). Double-buffered cp.async.
// ---------------------------------------------------------------------------
__global__ __launch_bounds__(256, 2)
void conv_mma(const float* __restrict__ bias) {
    __shared__ __align__(16) __nv_bfloat16 As[2][BM * BKP];
    __shared__ __align__(16) __nv_bfloat16 Bs[2][BK * SP];
    const int b = blockIdx.z, m0 = blockIdx.y * BM, n0 = blockIdx.x * BN;
    const int tid = threadIdx.x, lane = tid & 31, wid = tid >> 5;
    const int wm = wid >> 1, wn = wid & 1;
    const __nv_bfloat16* A = g_wpack;
    const __nv_bfloat16* Bm = g_im2col + (size_t)b * KTOT * HW;

    float acc[2][8][4];
#pragma unroll
    for (int i = 0; i < 2; i++)
#pragma unroll
        for (int j = 0; j < 8; j++)
#pragma unroll
            for (int q = 0; q < 4; q++) acc[i][j][q] = 0.f;

    const unsigned aBase = su32(As), bBase = su32(Bs);
    const int ar = tid >> 2, aq = tid & 3;          // A: 2 chunks/thread
    const int br = tid >> 4, bq = tid & 15;         // B: 2 chunks/thread

    auto issue = [&](int k0, int st) {
        unsigned ad = aBase + (unsigned)(st * BM * BKP + ar * BKP + aq * 8) * 2;
        const __nv_bfloat16* as = &A[(size_t)(m0 + ar) * KTOT + k0 + aq * 8];
        cp16(ad, as);
        cp16(ad + 64 * BKP * 2, as + (size_t)64 * KTOT);
        unsigned bd = bBase + (unsigned)(st * BK * SP + br * SP + bq * 8) * 2;
        const __nv_bfloat16* bs = &Bm[(size_t)(k0 + br) * HW + n0 + bq * 8];
        cp16(bd, bs);
        cp16(bd + 16 * SP * 2, bs + (size_t)16 * HW);
        CP_COMMIT();
    };

    issue(0, 0);
    const int S = KTOT / BK;
    for (int s = 0; s < S; s++) {
        CP_WAIT0();
        __syncthreads();
        if (s + 1 < S) issue((s + 1) * BK, (s + 1) & 1);
        mma_block<false, true>(aBase + (unsigned)((s & 1) * BM * BKP) * 2,
                               bBase + (unsigned)((s & 1) * BK * SP) * 2,
                               acc, lane, wm, wn);
    }

    __nv_bfloat16* out = g_qkv + (size_t)b * C3 * HW;
    const int rr = lane >> 2, cc = (lane & 3) * 2;
#pragma unroll
    for (int mi = 0; mi < 2; mi++) {
        int gr = m0 + wm * 32 + mi * 16 + rr;
        float b0v = bias[gr], b1v = bias[gr + 8];
#pragma unroll
        for (int n = 0; n < 8; n++) {
            int gc = n0 + wn * 64 + n * 8 + cc;
            *(__nv_bfloat162*)&out[(size_t)gr * HW + gc] =
                __floats2bfloat162_rn(acc[mi][n][0] + b0v, acc[mi][n][1] + b0v);
            *(__nv_bfloat162*)&out[(size_t)(gr + 8) * HW + gc] =
                __floats2bfloat162_rn(acc[mi][n][2] + b1v, acc[mi][n][3] + b1v);
        }
    }
}

// ---------------------------------------------------------------------------
// scores[qn][km] = scale * q^T k ; q,k are [c][p] (both k-major / trans)
// ---------------------------------------------------------------------------
__global__ __launch_bounds__(256, 2)
void scores_mma() {
    __shared__ __align__(16) __nv_bfloat16 As[2][BK * SP];
    __shared__ __align__(16) __nv_bfloat16 Bs[2][BK * SP];
    const int b = blockIdx.z, m0 = blockIdx.y * BM, n0 = blockIdx.x * BN;
    const int tid = threadIdx.x, lane = tid & 31, wid = tid >> 5;
    const int wm = wid >> 1, wn = wid & 1;
    const __nv_bfloat16* q = g_qkv + (size_t)b * C3 * HW;
    const __nv_bfloat16* km = q + (size_t)C * HW;

    float acc[2][8][4];
#pragma unroll
    for (int i = 0; i < 2; i++)
#pragma unroll
        for (int j = 0; j < 8; j++)
#pragma unroll
            for (int qq = 0; qq < 4; qq++) acc[i][j][qq] = 0.f;

    const unsigned aBase = su32(As), bBase = su32(Bs);
    const int r0 = tid >> 4, qd = tid & 15;

    auto issue = [&](int k0, int st) {
        unsigned off = (unsigned)(r0 * SP + qd * 8) * 2;
        unsigned ad = aBase + (unsigned)(st * BK * SP) * 2 + off;
        unsigned bd = bBase + (unsigned)(st * BK * SP) * 2 + off;
        const __nv_bfloat16* as = &q[(size_t)(k0 + r0) * HW + m0 + qd * 8];
        const __nv_bfloat16* bs = &km[(size_t)(k0 + r0) * HW + n0 + qd * 8];
        cp16(ad, as);                        cp16(bd, bs);
        cp16(ad + 16 * SP * 2, as + (size_t)16 * HW);
        cp16(bd + 16 * SP * 2, bs + (size_t)16 * HW);
        CP_COMMIT();
    };

    issue(0, 0);
    const int S = C / BK;
    for (int s = 0; s < S; s++) {
        CP_WAIT0();
        __syncthreads();
        if (s + 1 < S) issue((s + 1) * BK, (s + 1) & 1);
        mma_block<true, true>(aBase + (unsigned)((s & 1) * BK * SP) * 2,
                              bBase + (unsigned)((s & 1) * BK * SP) * 2,
                              acc, lane, wm, wn);
    }

    const float scale = 0.044194173824159216f;   // 512^-0.5
    float* sp = g_scores + (size_t)b * HW * HW;
    const int rr = lane >> 2, cc = (lane & 3) * 2;
#pragma unroll
    for (int mi = 0; mi < 2; mi++) {
        int gr = m0 + wm * 32 + mi * 16 + rr;
#pragma unroll
        for (int n = 0; n < 8; n++) {
            int gc = n0 + wn * 64 + n * 8 + cc;
            *(float2*)&sp[(size_t)gr * HW + gc] =
                make_float2(acc[mi][n][0] * scale, acc[mi][n][1] * scale);
            *(float2*)&sp[(size_t)(gr + 8) * HW + gc] =
                make_float2(acc[mi][n][2] * scale, acc[mi][n][3] * scale);
        }
    }
}

// ---------------------------------------------------------------------------
// Softmax over last axis (1024); fp32 in, bf16 out.
// ---------------------------------------------------------------------------
__global__ void softmax_kernel() {
    const float* s = g_scores + (size_t)blockIdx.x * HW;
    __nv_bfloat16* a = g_attn + (size_t)blockIdx.x * HW;
    const int tid = threadIdx.x, lane = tid & 31, wid = tid >> 5;
    __shared__ float red[32];

    float4 v = ((const float4*)s)[tid];
    float mx = fmaxf(fmaxf(v.x, v.y), fmaxf(v.z, v.w));
#pragma unroll
    for (int o = 16; o; o >>= 1) mx = fmaxf(mx, __shfl_xor_sync(0xffffffffu, mx, o));
    if (lane == 0) red[wid] = mx;
    __syncthreads();
    if (wid == 0) {
        float t = (lane < 8) ? red[lane] : -3.4e38f;
#pragma unroll
        for (int o = 4; o; o >>= 1) t = fmaxf(t, __shfl_xor_sync(0xffffffffu, t, o));
        if (lane == 0) red[0] = t;
    }
    __syncthreads();
    mx = red[0];
    __syncthreads();

    float4 e;
    e.x = expf(v.x - mx); e.y = expf(v.y - mx);
    e.z = expf(v.z - mx); e.w = expf(v.w - mx);
    float sum = e.x + e.y + e.z + e.w;
#pragma unroll
    for (int o = 16; o; o >>= 1) sum += __shfl_xor_sync(0xffffffffu, sum, o);
    if (lane == 0) red[wid] = sum;
    __syncthreads();
    if (wid == 0) {
        float t = (lane < 8) ? red[lane] : 0.f;
#pragma unroll
        for (int o = 4; o; o >>= 1) t += __shfl_xor_sync(0xffffffffu, t, o);
        if (lane == 0) red[0] = t;
    }
    __syncthreads();
    float inv = 1.0f / red[0];
    __nv_bfloat162 p0 = __floats2bfloat162_rn(e.x * inv, e.y * inv);
    __nv_bfloat162 p1 = __floats2bfloat162_rn(e.z * inv, e.w * inv);
    ((__nv_bfloat162*)a)[tid * 2] = p0;
    ((__nv_bfloat162*)a)[tid * 2 + 1] = p1;
}

// ---------------------------------------------------------------------------
// h[qn][c] = attn[qn][m] @ v[c][m]^T   A:[M][K] nt,  B:[N][K] nt
// ---------------------------------------------------------------------------
__global__ __launch_bounds__(256, 2)
void av_mma() {
    __shared__ __align__(16) __nv_bfloat16 As[2][BM * BKP];
    __shared__ __align__(16) __nv_bfloat16 Bs[2][BN * BKP];
    const int b = blockIdx.z, m0 = blockIdx.y * BM, n0 = blockIdx.x * BN;
    const int tid = threadIdx.x, lane = tid & 31, wid = tid >> 5;
    const int wm = wid >> 1, wn = wid & 1;
    const __nv_bfloat16* attn = g_attn + (size_t)b * HW * HW;
    const __nv_bfloat16* v = g_qkv + (size_t)b * C3 * HW + (size_t)2 * C * HW;

    float acc[2][8][4];
#pragma unroll
    for (int i = 0; i < 2; i++)
#pragma unroll
        for (int j = 0; j < 8; j++)
#pragma unroll
            for (int q = 0; q < 4; q++) acc[i][j][q] = 0.f;

    const unsigned aBase = su32(As), bBase = su32(Bs);
    const int ar = tid >> 2, aq = tid & 3;

    auto issue = [&](int k0, int st) {
        unsigned off = (unsigned)(ar * BKP + aq * 8) * 2;
        unsigned ad = aBase + (unsigned)(st * BM * BKP) * 2 + off;
        unsigned bd = bBase + (unsigned)(st * BN * BKP) * 2 + off;
        const __nv_bfloat16* as = &attn[(size_t)(m0 + ar) * HW + k0 + aq * 8];
        const __nv_bfloat16* bs = &v[(size_t)(n0 + ar) * HW + k0 + aq * 8];
        cp16(ad, as);                                 cp16(bd, bs);
        cp16(ad + 64 * BKP * 2, as + (size_t)64 * HW);
        cp16(bd + 64 * BKP * 2, bs + (size_t)64 * HW);
        CP_COMMIT();
    };

    issue(0, 0);
    const int S = HW / BK;
    for (int s = 0; s < S; s++) {
        CP_WAIT0();
        __syncthreads();
        if (s + 1 < S) issue((s + 1) * BK, (s + 1) & 1);
        mma_block<false, false>(aBase + (unsigned)((s & 1) * BM * BKP) * 2,
                                bBase + (unsigned)((s & 1) * BN * BKP) * 2,
                                acc, lane, wm, wn);
    }

    __nv_bfloat16* hp = g_h + (size_t)b * HW * C;
    const int rr = lane >> 2, cc = (lane & 3) * 2;
#pragma unroll
    for (int mi = 0; mi < 2; mi++) {
        int gr = m0 + wm * 32 + mi * 16 + rr;
#pragma unroll
        for (int n = 0; n < 8; n++) {
            int gc = n0 + wn * 64 + n * 8 + cc;
            *(__nv_bfloat162*)&hp[(size_t)gr * C + gc] =
                __floats2bfloat162_rn(acc[mi][n][0], acc[mi][n][1]);
            *(__nv_bfloat162*)&hp[(size_t)(gr + 8) * C + gc] =
                __floats2bfloat162_rn(acc[mi][n][2], acc[mi][n][3]);
        }
    }
}

// ---------------------------------------------------------------------------
// out[co][p] = x[co][p] + b_proj[co] + wproj[co][ci] @ h[p][ci]^T  (fp32 out)
// ---------------------------------------------------------------------------
__global__ __launch_bounds__(256, 2)
void proj_mma(const float* __restrict__ x, const float* __restrict__ bproj,
              float* __restrict__ out) {
    __shared__ __align__(16) __nv_bfloat16 As[2][BM * BKP];
    __shared__ __align__(16) __nv_bfloat16 Bs[2][BN * BKP];
    const int b = blockIdx.z, m0 = blockIdx.y * BM, n0 = blockIdx.x * BN;
    const int tid = threadIdx.x, lane = tid & 31, wid = tid >> 5;
    const int wm = wid >> 1, wn = wid & 1;
    const __nv_bfloat16* hp = g_h + (size_t)b * HW * C;

    float acc[2][8][4];
#pragma unroll
    for (int i = 0; i < 2; i++)
#pragma unroll
        for (int j = 0; j < 8; j++)
#pragma unroll
            for (int q = 0; q < 4; q++) acc[i][j][q] = 0.f;

    const unsigned aBase = su32(As), bBase = su32(Bs);
    const int ar = tid >> 2, aq = tid & 3;

    auto issue = [&](int k0, int st) {
        unsigned off = (unsigned)(ar * BKP + aq * 8) * 2;
        unsigned ad = aBase + (unsigned)(st * BM * BKP) * 2 + off;
        unsigned bd = bBase + (unsigned)(st * BN * BKP) * 2 + off;
        const __nv_bfloat16* as = &g_wproj[(size_t)(m0 + ar) * C + k0 + aq * 8];
        const __nv_bfloat16* bs = &hp[(size_t)(n0 + ar) * C + k0 + aq * 8];
        cp16(ad, as);                                cp16(bd, bs);
        cp16(ad + 64 * BKP * 2, as + (size_t)64 * C);
        cp16(bd + 64 * BKP * 2, bs + (size_t)64 * C);
        CP_COMMIT();
    };

    issue(0, 0);
    const int S = C / BK;
    for (int s = 0; s < S; s++) {
        CP_WAIT0();
        __syncthreads();
        if (s + 1 < S) issue((s + 1) * BK, (s + 1) & 1);
        mma_block<false, false>(aBase + (unsigned)((s & 1) * BM * BKP) * 2,
                                bBase + (unsigned)((s & 1) * BN * BKP) * 2,
                                acc, lane, wm, wn);
    }

    const float* xb = x + (size_t)b * C * HW;
    float* ob = out + (size_t)b * C * HW;
    const int rr = lane >> 2, cc = (lane & 3) * 2;
#pragma unroll
    for (int mi = 0; mi < 2; mi++) {
        int gr = m0 + wm * 32 + mi * 16 + rr;
        float b0v = bproj[gr], b1v = bproj[gr + 8];
#pragma unroll
        for (int n = 0; n < 8; n++) {
            int gc = n0 + wn * 64 + n * 8 + cc;
            float2 x0 = *(const float2*)&xb[(size_t)gr * HW + gc];
            float2 x1 = *(const float2*)&xb[(size_t)(gr + 8) * HW + gc];
            *(float2*)&ob[(size_t)gr * HW + gc] =
                make_float2(x0.x + b0v + acc[mi][n][0], x0.y + b0v + acc[mi][n][1]);
            *(float2*)&ob[(size_t)(gr + 8) * HW + gc] =
                make_float2(x1.x + b1v + acc[mi][n][2], x1.y + b1v + acc[mi][n][3]);
        }
    }
}

// ---------------------------------------------------------------------------
extern "C" void kernel_launch(void* const* d_in, const int* in_sizes, int n_in,
                              void* d_out, int out_size) {
    const float* x      = (const float*)d_in[0];
    const float* w_qkv  = (const float*)d_in[1];
    const float* b_qkv  = (const float*)d_in[2];
    const float* w_proj = (const float*)d_in[3];
    const float* b_proj = (const float*)d_in[4];
    float* out = (float*)d_out;

    pack_w_kernel<<<(C3 * KTOT + 255) / 256, 256>>>(w_qkv);
    pack_wproj_kernel<<<(C * C + 255) / 256, 256>>>(w_proj);
    {
        size_t total = (size_t)Bsz * KTOT * 128;   // 8 pixels per thread
        im2col_kernel<<<(unsigned)((total + 255) / 256), 256>>>(x);
    }
    conv_mma<<<dim3(HW / BN, C3 / BM, Bsz), 256>>>(b_qkv);
    scores_mma<<<dim3(HW / BN, HW / BM, Bsz), 256>>>();
    softmax_kernel<<<Bsz * HW, 256>>>();
    av_mma<<<dim3(C / BN, HW / BM, Bsz), 256>>>();
    proj_mma<<<dim3(HW / BN, C / BM, Bsz), 256>>>(x, b_proj, out);
}